// round 12
// baseline (speedup 1.0000x reference)
#include <cuda_runtime.h>
#include <cstdint>

// HashEmbedder: Instant-NGP multiresolution hash grid encoding.
// R12:
//  - CG_FROM 11 -> 9: levels 9-10 also L2-only, so level <=8 corner lines
//    (~190KB per SM region) stay L1-resident (R11 showed fine-level policy
//    itself is cost-neutral; the win is what it stops evicting).
//  - __ldcs on g_sorted reads, __stcs on out stores (read-once/write-once
//    streams stop evicting table lines from L2).
//  - count kernel: 4 points/thread via 3x float4 loads (1/4 the LDG+STG
//    instructions, same bytes).
// Keeps: Morton sort, atomic-free scatter, fused decoupled scan, exact
// multiplies, SM-affinity remap, 2-stage pipelined hashgrid (256,4).

#define MAXPTS    524288
#define NBINS_DIM 32
#define NBINS     (NBINS_DIM * NBINS_DIM * NBINS_DIM)   // 32768 = 2^15
#define CHUNK     128
#define NCHUNKS   (NBINS / CHUNK)                        // 256
#define N_LEVELS  16
#define TABLE_SZ  (1u << 19)
#define TMASK     (TABLE_SZ - 1u)
#define NSM       148
#define CG_FROM   9    // levels >= this use __ldcg (L2-only)

// scratch (allocations forbidden); zero-initialized at module load
__device__ unsigned g_count[NBINS];
__device__ unsigned g_local[NBINS];     // exclusive prefix within chunk
__device__ unsigned g_partial[NCHUNKS]; // per-chunk totals
__device__ unsigned g_base[NCHUNKS];    // exclusive scan of chunk totals
__device__ unsigned g_arrive;           // decoupled-scan arrival ticket
__device__ unsigned g_binrank[MAXPTS];  // bin (15b) | rank<<15
__device__ float4   g_sorted[MAXPTS];   // xyz + original index (int bits)

// res/2 = 0.5*floor(16*cbrt(2)^i): all exactly representable in fp32
__device__ __constant__ float c_resh[N_LEVELS] = {
    8.f, 10.f, 12.5f, 16.f, 20.f, 25.f, 32.f, 40.f,
    50.5f, 64.f, 80.5f, 101.5f, 128.f, 161.f, 203.f, 256.f
};

__device__ __forceinline__ unsigned part1by2(unsigned x) {
    x &= 0x3FF;
    x = (x | (x << 16)) & 0x030000FF;
    x = (x | (x << 8))  & 0x0300F00F;
    x = (x | (x << 4))  & 0x030C30C3;
    x = (x | (x << 2))  & 0x09249249;
    return x;
}

__device__ __forceinline__ unsigned bin_of(float x, float y, float z) {
    int cx = (int)((x + 1.0f) * 16.0f);
    int cy = (int)((y + 1.0f) * 16.0f);
    int cz = (int)((z + 1.0f) * 16.0f);
    cx = min(max(cx, 0), 31);
    cy = min(max(cy, 0), 31);
    cz = min(max(cz, 0), 31);
    return part1by2((unsigned)cx) | (part1by2((unsigned)cy) << 1) |
           (part1by2((unsigned)cz) << 2);
}

// histogram + capture rank; 4 points per thread via 3x float4 loads.
// n is a multiple of 4 here (524288); guarded per-point anyway.
__global__ void count_kernel(const float4* __restrict__ pts4, int n) {
    int base = (blockIdx.x * blockDim.x + threadIdx.x) * 4;
    if (base >= n) return;
    // 4 points = 12 floats = 3 float4s
    int fi = base * 3 / 4;            // float4 index of first 16B
    float4 a = __ldcs(pts4 + fi);
    float4 b = __ldcs(pts4 + fi + 1);
    float4 c = __ldcs(pts4 + fi + 2);
    float px[4] = {a.x, a.w, b.z, c.y};
    float py[4] = {a.y, b.x, b.w, c.z};
    float pz[4] = {a.z, b.y, c.x, c.w};
#pragma unroll
    for (int k = 0; k < 4; k++) {
        int i = base + k;
        if (i >= n) break;
        unsigned bb = bin_of(px[k], py[k], pz[k]);
        unsigned rank = atomicAdd(&g_count[bb], 1u);
        g_binrank[i] = bb | (rank << 15);
    }
}

// per-chunk exclusive scan (256 blocks x 128 threads, 1 bin/thread);
// last-arriving block also scans the 256 chunk totals into g_base.
// Resets g_count and g_arrive so each call/replay starts clean.
__global__ __launch_bounds__(CHUNK)
void scan_kernel() {
    __shared__ unsigned sh[CHUNK];
    __shared__ bool is_last;
    int bin = blockIdx.x * CHUNK + threadIdx.x;
    int t = threadIdx.x;

    unsigned v = g_count[bin];
    g_count[bin] = 0;                    // reset for next call
    sh[t] = v;
    __syncthreads();
#pragma unroll
    for (int d = 1; d < CHUNK; d <<= 1) {
        unsigned x = (t >= d) ? sh[t - d] : 0u;
        __syncthreads();
        sh[t] += x;
        __syncthreads();
    }
    g_local[bin] = sh[t] - v;            // exclusive within chunk
    if (t == CHUNK - 1) g_partial[blockIdx.x] = sh[t];

    __threadfence();
    if (t == 0)
        is_last = (atomicAdd(&g_arrive, 1u) == NCHUNKS - 1);
    __syncthreads();
    if (is_last) {
        unsigned p0 = g_partial[2 * t];
        unsigned p1 = g_partial[2 * t + 1];
        unsigned s = p0 + p1;
        sh[t] = s;
        __syncthreads();
#pragma unroll
        for (int d = 1; d < CHUNK; d <<= 1) {
            unsigned x = (t >= d) ? sh[t - d] : 0u;
            __syncthreads();
            sh[t] += x;
            __syncthreads();
        }
        unsigned base = sh[t] - s;
        g_base[2 * t]     = base;
        g_base[2 * t + 1] = base + p0;
        if (t == 0) g_arrive = 0;        // reset ticket for next call
    }
}

// atomic-free scatter: pos = base[chunk] + local[bin] + rank
__global__ void scatter_kernel(const float* __restrict__ pts, int n) {
    int i = blockIdx.x * blockDim.x + threadIdx.x;
    if (i >= n) return;
    unsigned br = g_binrank[i];
    unsigned bin = br & 0x7FFFu;
    unsigned pos = g_base[bin >> 7] + g_local[bin] + (br >> 15);
    float x = pts[3 * i + 0], y = pts[3 * i + 1], z = pts[3 * i + 2];
    g_sorted[pos] = make_float4(x, y, z, __int_as_float(i));
}

__device__ __forceinline__ float2 lerp2(float2 a, float2 b, float t) {
    float2 r;
    r.x = a.x + t * (b.x - a.x);
    r.y = a.y + t * (b.y - a.y);
    return r;
}

// issue the 8 corner gathers + weights for level `lv` into buffer `buf`.
#define LOAD_LEVEL_OP(lv, buf, LDOP)                                         \
    do {                                                                     \
        float rh = c_resh[lv];                                               \
        float sx = ax * rh, sy = ay * rh, sz = az * rh;                      \
        int ixi = __float2int_rd(sx);                                        \
        int iyi = __float2int_rd(sy);                                        \
        int izi = __float2int_rd(sz);                                        \
        wbx[buf] = sx - (float)ixi;                                          \
        wby[buf] = sy - (float)iyi;                                          \
        wbz[buf] = sz - (float)izi;                                          \
        unsigned hx0 = (unsigned)ixi * P0, hx1 = hx0 + P0;                   \
        unsigned hy0 = (unsigned)iyi * P1, hy1 = hy0 + P1;                   \
        unsigned hz0 = (unsigned)izi * P2, hz1 = hz0 + P2;                   \
        const float2* t = tables + (size_t)(lv) * TABLE_SZ;                  \
        cbuf[buf][0] = LDOP(t + ((hx0 ^ hy0 ^ hz0) & TMASK));                \
        cbuf[buf][1] = LDOP(t + ((hx0 ^ hy0 ^ hz1) & TMASK));                \
        cbuf[buf][2] = LDOP(t + ((hx0 ^ hy1 ^ hz0) & TMASK));                \
        cbuf[buf][3] = LDOP(t + ((hx0 ^ hy1 ^ hz1) & TMASK));                \
        cbuf[buf][4] = LDOP(t + ((hx1 ^ hy0 ^ hz0) & TMASK));                \
        cbuf[buf][5] = LDOP(t + ((hx1 ^ hy0 ^ hz1) & TMASK));                \
        cbuf[buf][6] = LDOP(t + ((hx1 ^ hy1 ^ hz0) & TMASK));                \
        cbuf[buf][7] = LDOP(t + ((hx1 ^ hy1 ^ hz1) & TMASK));                \
    } while (0)

__global__ __launch_bounds__(256, 4)
void hashgrid_kernel(const float2* __restrict__ tables,
                     float4* __restrict__ out,   // [n, 8] float4
                     int n)
{
    // SM-affinity remap: blocks sharing an SM (bid % 148) get consecutive
    // sorted segments -> each SM's corner working set is one Morton region.
    int G = gridDim.x;
    int b = blockIdx.x;
    int g = b % NSM;
    int i = b / NSM;
    int q = G / NSM, r = G % NSM;
    int seg = g * q + min(g, r) + i;

    int s = seg * (int)blockDim.x + threadIdx.x;
    if (s >= n) return;

    float4 f = __ldcs(&g_sorted[s]);   // read-once stream
    int orig = __float_as_int(f.w);

    float ax = f.x + 1.0f;
    float ay = f.y + 1.0f;
    float az = f.z + 1.0f;

    const unsigned P0 = 73856093u, P1 = 19349663u, P2 = 83492791u;

    float2 cbuf[2][8];
    float wbx[2], wby[2], wbz[2];

    LOAD_LEVEL_OP(0, 0, __ldg);   // prologue: level 0 in flight

    float4* o = out + (size_t)orig * (N_LEVELS / 2);
    float4 acc;

#pragma unroll
    for (int l = 0; l < N_LEVELS; l++) {
        const int cur = l & 1;
        const int nxt = cur ^ 1;

        // issue next level's gathers BEFORE consuming this level's corners;
        // levels >= CG_FROM are L2-only so coarse/mid lines stay in L1.
        if (l + 1 < N_LEVELS) {
            if (l + 1 >= CG_FROM) LOAD_LEVEL_OP(l + 1, nxt, __ldcg);
            else                  LOAD_LEVEL_OP(l + 1, nxt, __ldg);
        }

        float wx = wbx[cur], wy = wby[cur], wz = wbz[cur];
        float2 c00 = lerp2(cbuf[cur][0], cbuf[cur][1], wz);
        float2 c01 = lerp2(cbuf[cur][2], cbuf[cur][3], wz);
        float2 c10 = lerp2(cbuf[cur][4], cbuf[cur][5], wz);
        float2 c11 = lerp2(cbuf[cur][6], cbuf[cur][7], wz);
        float2 c0  = lerp2(c00, c01, wy);
        float2 c1  = lerp2(c10, c11, wy);
        float2 r2  = lerp2(c0, c1, wx);

        if ((l & 1) == 0) {
            acc.x = r2.x; acc.y = r2.y;
        } else {
            acc.z = r2.x; acc.w = r2.y;
            __stcs(o + (l >> 1), acc);   // write-once stream
        }
    }
}

extern "C" void kernel_launch(void* const* d_in, const int* in_sizes, int n_in,
                              void* d_out, int out_size)
{
    const float*  pts    = (const float*)d_in[0];   // [n, 3]
    const float2* tables = (const float2*)d_in[1];  // [16, 2^19] float2
    float4*       out    = (float4*)d_out;          // [n, 8] float4

    int n = in_sizes[0] / 3;
    if (n > MAXPTS) n = MAXPTS;

    int T = 256;
    int gp  = (n + T - 1) / T;
    int gp4 = (n / 4 + T - 1) / T;   // count: 4 points per thread

    count_kernel<<<gp4, T>>>((const float4*)pts, n);
    scan_kernel<<<NCHUNKS, CHUNK>>>();
    scatter_kernel<<<gp, T>>>(pts, n);
    hashgrid_kernel<<<gp, T>>>(tables, out, n);
}

// round 13
// speedup vs baseline: 1.0428x; 1.0428x over previous
#include <cuda_runtime.h>
#include <cstdint>

// HashEmbedder: Instant-NGP multiresolution hash grid encoding.
// R13 = best measured config of every component:
//  - hashgrid: exact R11 form (2-stage pipeline, CG_FROM=11, plain loads/
//    stores). R12 proved levels 9-10 have real L1 reuse (demoting them to
//    L2-only cost 9us) and streaming hints on conveyor/output don't help.
//  - count: R12's 4-points/thread vectorized form (kept; -0.7us measured).
//  - fused decoupled scan, atomic-free scatter, Morton sort, exact
//    multiplies, SM-affinity remap.

#define MAXPTS    524288
#define NBINS_DIM 32
#define NBINS     (NBINS_DIM * NBINS_DIM * NBINS_DIM)   // 32768 = 2^15
#define CHUNK     128
#define NCHUNKS   (NBINS / CHUNK)                        // 256
#define N_LEVELS  16
#define TABLE_SZ  (1u << 19)
#define TMASK     (TABLE_SZ - 1u)
#define NSM       148
#define CG_FROM   11   // levels >= this use __ldcg (L2-only); measured neutral
                       // but keeps fine levels out of L1 without harm

// scratch (allocations forbidden); zero-initialized at module load
__device__ unsigned g_count[NBINS];
__device__ unsigned g_local[NBINS];     // exclusive prefix within chunk
__device__ unsigned g_partial[NCHUNKS]; // per-chunk totals
__device__ unsigned g_base[NCHUNKS];    // exclusive scan of chunk totals
__device__ unsigned g_arrive;           // decoupled-scan arrival ticket
__device__ unsigned g_binrank[MAXPTS];  // bin (15b) | rank<<15
__device__ float4   g_sorted[MAXPTS];   // xyz + original index (int bits)

// res/2 = 0.5*floor(16*cbrt(2)^i): all exactly representable in fp32
__device__ __constant__ float c_resh[N_LEVELS] = {
    8.f, 10.f, 12.5f, 16.f, 20.f, 25.f, 32.f, 40.f,
    50.5f, 64.f, 80.5f, 101.5f, 128.f, 161.f, 203.f, 256.f
};

__device__ __forceinline__ unsigned part1by2(unsigned x) {
    x &= 0x3FF;
    x = (x | (x << 16)) & 0x030000FF;
    x = (x | (x << 8))  & 0x0300F00F;
    x = (x | (x << 4))  & 0x030C30C3;
    x = (x | (x << 2))  & 0x09249249;
    return x;
}

__device__ __forceinline__ unsigned bin_of(float x, float y, float z) {
    int cx = (int)((x + 1.0f) * 16.0f);
    int cy = (int)((y + 1.0f) * 16.0f);
    int cz = (int)((z + 1.0f) * 16.0f);
    cx = min(max(cx, 0), 31);
    cy = min(max(cy, 0), 31);
    cz = min(max(cz, 0), 31);
    return part1by2((unsigned)cx) | (part1by2((unsigned)cy) << 1) |
           (part1by2((unsigned)cz) << 2);
}

// histogram + capture rank; 4 points per thread via 3x float4 loads.
__global__ void count_kernel(const float4* __restrict__ pts4, int n) {
    int base = (blockIdx.x * blockDim.x + threadIdx.x) * 4;
    if (base >= n) return;
    int fi = base * 3 / 4;            // float4 index of first 16B
    float4 a = pts4[fi];
    float4 b = pts4[fi + 1];
    float4 c = pts4[fi + 2];
    float px[4] = {a.x, a.w, b.z, c.y};
    float py[4] = {a.y, b.x, b.w, c.z};
    float pz[4] = {a.z, b.y, c.x, c.w};
#pragma unroll
    for (int k = 0; k < 4; k++) {
        int i = base + k;
        if (i >= n) break;
        unsigned bb = bin_of(px[k], py[k], pz[k]);
        unsigned rank = atomicAdd(&g_count[bb], 1u);
        g_binrank[i] = bb | (rank << 15);
    }
}

// per-chunk exclusive scan (256 blocks x 128 threads, 1 bin/thread);
// last-arriving block also scans the 256 chunk totals into g_base.
// Resets g_count and g_arrive so each call/replay starts clean.
__global__ __launch_bounds__(CHUNK)
void scan_kernel() {
    __shared__ unsigned sh[CHUNK];
    __shared__ bool is_last;
    int bin = blockIdx.x * CHUNK + threadIdx.x;
    int t = threadIdx.x;

    unsigned v = g_count[bin];
    g_count[bin] = 0;                    // reset for next call
    sh[t] = v;
    __syncthreads();
#pragma unroll
    for (int d = 1; d < CHUNK; d <<= 1) {
        unsigned x = (t >= d) ? sh[t - d] : 0u;
        __syncthreads();
        sh[t] += x;
        __syncthreads();
    }
    g_local[bin] = sh[t] - v;            // exclusive within chunk
    if (t == CHUNK - 1) g_partial[blockIdx.x] = sh[t];

    __threadfence();
    if (t == 0)
        is_last = (atomicAdd(&g_arrive, 1u) == NCHUNKS - 1);
    __syncthreads();
    if (is_last) {
        unsigned p0 = g_partial[2 * t];
        unsigned p1 = g_partial[2 * t + 1];
        unsigned s = p0 + p1;
        sh[t] = s;
        __syncthreads();
#pragma unroll
        for (int d = 1; d < CHUNK; d <<= 1) {
            unsigned x = (t >= d) ? sh[t - d] : 0u;
            __syncthreads();
            sh[t] += x;
            __syncthreads();
        }
        unsigned base = sh[t] - s;
        g_base[2 * t]     = base;
        g_base[2 * t + 1] = base + p0;
        if (t == 0) g_arrive = 0;        // reset ticket for next call
    }
}

// atomic-free scatter: pos = base[chunk] + local[bin] + rank
__global__ void scatter_kernel(const float* __restrict__ pts, int n) {
    int i = blockIdx.x * blockDim.x + threadIdx.x;
    if (i >= n) return;
    unsigned br = g_binrank[i];
    unsigned bin = br & 0x7FFFu;
    unsigned pos = g_base[bin >> 7] + g_local[bin] + (br >> 15);
    float x = pts[3 * i + 0], y = pts[3 * i + 1], z = pts[3 * i + 2];
    g_sorted[pos] = make_float4(x, y, z, __int_as_float(i));
}

__device__ __forceinline__ float2 lerp2(float2 a, float2 b, float t) {
    float2 r;
    r.x = a.x + t * (b.x - a.x);
    r.y = a.y + t * (b.y - a.y);
    return r;
}

// issue the 8 corner gathers + weights for level `lv` into buffer `buf`.
#define LOAD_LEVEL_OP(lv, buf, LDOP)                                         \
    do {                                                                     \
        float rh = c_resh[lv];                                               \
        float sx = ax * rh, sy = ay * rh, sz = az * rh;                      \
        int ixi = __float2int_rd(sx);                                        \
        int iyi = __float2int_rd(sy);                                        \
        int izi = __float2int_rd(sz);                                        \
        wbx[buf] = sx - (float)ixi;                                          \
        wby[buf] = sy - (float)iyi;                                          \
        wbz[buf] = sz - (float)izi;                                          \
        unsigned hx0 = (unsigned)ixi * P0, hx1 = hx0 + P0;                   \
        unsigned hy0 = (unsigned)iyi * P1, hy1 = hy0 + P1;                   \
        unsigned hz0 = (unsigned)izi * P2, hz1 = hz0 + P2;                   \
        const float2* t = tables + (size_t)(lv) * TABLE_SZ;                  \
        cbuf[buf][0] = LDOP(t + ((hx0 ^ hy0 ^ hz0) & TMASK));                \
        cbuf[buf][1] = LDOP(t + ((hx0 ^ hy0 ^ hz1) & TMASK));                \
        cbuf[buf][2] = LDOP(t + ((hx0 ^ hy1 ^ hz0) & TMASK));                \
        cbuf[buf][3] = LDOP(t + ((hx0 ^ hy1 ^ hz1) & TMASK));                \
        cbuf[buf][4] = LDOP(t + ((hx1 ^ hy0 ^ hz0) & TMASK));                \
        cbuf[buf][5] = LDOP(t + ((hx1 ^ hy0 ^ hz1) & TMASK));                \
        cbuf[buf][6] = LDOP(t + ((hx1 ^ hy1 ^ hz0) & TMASK));                \
        cbuf[buf][7] = LDOP(t + ((hx1 ^ hy1 ^ hz1) & TMASK));                \
    } while (0)

__global__ __launch_bounds__(256, 4)
void hashgrid_kernel(const float2* __restrict__ tables,
                     float4* __restrict__ out,   // [n, 8] float4
                     int n)
{
    // SM-affinity remap: blocks sharing an SM (bid % 148) get consecutive
    // sorted segments -> each SM's corner working set is one Morton region.
    int G = gridDim.x;
    int b = blockIdx.x;
    int g = b % NSM;
    int i = b / NSM;
    int q = G / NSM, r = G % NSM;
    int seg = g * q + min(g, r) + i;

    int s = seg * (int)blockDim.x + threadIdx.x;
    if (s >= n) return;

    float4 f = g_sorted[s];
    int orig = __float_as_int(f.w);

    float ax = f.x + 1.0f;
    float ay = f.y + 1.0f;
    float az = f.z + 1.0f;

    const unsigned P0 = 73856093u, P1 = 19349663u, P2 = 83492791u;

    float2 cbuf[2][8];
    float wbx[2], wby[2], wbz[2];

    LOAD_LEVEL_OP(0, 0, __ldg);   // prologue: level 0 in flight

    float4* o = out + (size_t)orig * (N_LEVELS / 2);
    float4 acc;

#pragma unroll
    for (int l = 0; l < N_LEVELS; l++) {
        const int cur = l & 1;
        const int nxt = cur ^ 1;

        // issue next level's gathers BEFORE consuming this level's corners
        if (l + 1 < N_LEVELS) {
            if (l + 1 >= CG_FROM) LOAD_LEVEL_OP(l + 1, nxt, __ldcg);
            else                  LOAD_LEVEL_OP(l + 1, nxt, __ldg);
        }

        float wx = wbx[cur], wy = wby[cur], wz = wbz[cur];
        float2 c00 = lerp2(cbuf[cur][0], cbuf[cur][1], wz);
        float2 c01 = lerp2(cbuf[cur][2], cbuf[cur][3], wz);
        float2 c10 = lerp2(cbuf[cur][4], cbuf[cur][5], wz);
        float2 c11 = lerp2(cbuf[cur][6], cbuf[cur][7], wz);
        float2 c0  = lerp2(c00, c01, wy);
        float2 c1  = lerp2(c10, c11, wy);
        float2 r2  = lerp2(c0, c1, wx);

        if ((l & 1) == 0) {
            acc.x = r2.x; acc.y = r2.y;
        } else {
            acc.z = r2.x; acc.w = r2.y;
            o[l >> 1] = acc;
        }
    }
}

extern "C" void kernel_launch(void* const* d_in, const int* in_sizes, int n_in,
                              void* d_out, int out_size)
{
    const float*  pts    = (const float*)d_in[0];   // [n, 3]
    const float2* tables = (const float2*)d_in[1];  // [16, 2^19] float2
    float4*       out    = (float4*)d_out;          // [n, 8] float4

    int n = in_sizes[0] / 3;
    if (n > MAXPTS) n = MAXPTS;

    int T = 256;
    int gp  = (n + T - 1) / T;
    int gp4 = (n / 4 + T - 1) / T;   // count: 4 points per thread

    count_kernel<<<gp4, T>>>((const float4*)pts, n);
    scan_kernel<<<NCHUNKS, CHUNK>>>();
    scatter_kernel<<<gp, T>>>(pts, n);
    hashgrid_kernel<<<gp, T>>>(tables, out, n);
}